// round 8
// baseline (speedup 1.0000x reference)
#include <cuda_runtime.h>
#include <cuda_bf16.h>

// Problem shape (fixed by the dataset): [B=32, C=1, H=1024, W=1024] fp32.
#define B_DIM 32
#define HW (1024 * 1024)
#define HW4 (HW / 4)          // 262144 float4 pixels
#define HALF (HW4 / 2)        // 131072 threads: each handles pix4 and pix4+HALF
#define TPB 128
#define GRID (HALF / TPB)     // 1024 blocks of 128 -> 6.92 blocks/SM, 1 wave
#define LAMBDA 0.1

// Global accumulators: [0]=diff2, [1]=G2, [2]=H2. Zero at module load; the
// last block of each launch resets them, so every graph replay starts clean.
__device__ double g_acc[3];
__device__ unsigned int g_count;

__global__ __launch_bounds__(TPB, 8) void praloss_fused_kernel(
    const float4* __restrict__ est, const float4* __restrict__ gt,
    float* __restrict__ out)
{
    const int pix4 = blockIdx.x * TPB + threadIdx.x;  // 0 .. HALF-1

    // Per-pixel accumulators for two pixels: sum(e-g), sum e^2, sum (e-g)^2.
    float4 sd0 = make_float4(0.f, 0.f, 0.f, 0.f);
    float4 qe0 = make_float4(0.f, 0.f, 0.f, 0.f);
    float4 qd0 = make_float4(0.f, 0.f, 0.f, 0.f);
    float4 sd1 = make_float4(0.f, 0.f, 0.f, 0.f);
    float4 qe1 = make_float4(0.f, 0.f, 0.f, 0.f);
    float4 qd1 = make_float4(0.f, 0.f, 0.f, 0.f);

    const float4* pe = est + pix4;
    const float4* pg = gt  + pix4;

    #pragma unroll 4
    for (int b = 0; b < B_DIM; b++) {
        const long off = (long)b * HW4;
        const float4 e0 = pe[off];
        const float4 g0 = pg[off];
        const float4 e1 = pe[off + HALF];
        const float4 g1 = pg[off + HALF];

        float dx, dy, dz, dw;
        dx = e0.x - g0.x; dy = e0.y - g0.y; dz = e0.z - g0.z; dw = e0.w - g0.w;
        sd0.x += dx; sd0.y += dy; sd0.z += dz; sd0.w += dw;
        qd0.x = fmaf(dx, dx, qd0.x); qd0.y = fmaf(dy, dy, qd0.y);
        qd0.z = fmaf(dz, dz, qd0.z); qd0.w = fmaf(dw, dw, qd0.w);
        qe0.x = fmaf(e0.x, e0.x, qe0.x); qe0.y = fmaf(e0.y, e0.y, qe0.y);
        qe0.z = fmaf(e0.z, e0.z, qe0.z); qe0.w = fmaf(e0.w, e0.w, qe0.w);

        dx = e1.x - g1.x; dy = e1.y - g1.y; dz = e1.z - g1.z; dw = e1.w - g1.w;
        sd1.x += dx; sd1.y += dy; sd1.z += dz; sd1.w += dw;
        qd1.x = fmaf(dx, dx, qd1.x); qd1.y = fmaf(dy, dy, qd1.y);
        qd1.z = fmaf(dz, dz, qd1.z); qd1.w = fmaf(dw, dw, qd1.w);
        qe1.x = fmaf(e1.x, e1.x, qe1.x); qe1.y = fmaf(e1.y, e1.y, qe1.y);
        qe1.z = fmaf(e1.z, e1.z, qe1.z); qe1.w = fmaf(e1.w, e1.w, qe1.w);
    }

    float diff2 = (qd0.x + qd0.y) + (qd0.z + qd0.w)
                + (qd1.x + qd1.y) + (qd1.z + qd1.w);
    float G2    = (qe0.x + qe0.y) + (qe0.z + qe0.w)
                + (qe1.x + qe1.y) + (qe1.z + qe1.w);
    // mask: sum(est) > sum(gt) <=> sum(est-gt) > 0 (up to fp rounding)
    float H2    = (sd0.x > 0.f ? qe0.x : 0.f)
                + (sd0.y > 0.f ? qe0.y : 0.f)
                + (sd0.z > 0.f ? qe0.z : 0.f)
                + (sd0.w > 0.f ? qe0.w : 0.f)
                + (sd1.x > 0.f ? qe1.x : 0.f)
                + (sd1.y > 0.f ? qe1.y : 0.f)
                + (sd1.z > 0.f ? qe1.z : 0.f)
                + (sd1.w > 0.f ? qe1.w : 0.f);

    // Warp reduce (3 scalars)
    #pragma unroll
    for (int off = 16; off > 0; off >>= 1) {
        diff2 += __shfl_down_sync(0xFFFFFFFFu, diff2, off);
        G2    += __shfl_down_sync(0xFFFFFFFFu, G2,    off);
        H2    += __shfl_down_sync(0xFFFFFFFFu, H2,    off);
    }

    // Block reduce via shared memory (4 warps per 128-thread block)
    __shared__ float sm[3][4];
    const int lane = threadIdx.x & 31;
    const int wid  = threadIdx.x >> 5;
    if (lane == 0) {
        sm[0][wid] = diff2; sm[1][wid] = G2; sm[2][wid] = H2;
    }
    __syncthreads();

    if (threadIdx.x == 0) {
        float v0 = 0.f, v1 = 0.f, v2 = 0.f;
        #pragma unroll
        for (int w = 0; w < 4; w++) {
            v0 += sm[0][w]; v1 += sm[1][w]; v2 += sm[2][w];
        }
        atomicAdd(&g_acc[0], (double)v0);
        atomicAdd(&g_acc[1], (double)v1);
        atomicAdd(&g_acc[2], (double)v2);

        // Order this block's accumulator atomics before the ticket.
        __threadfence();
        unsigned int old = atomicAdd(&g_count, 1u);
        if (old == (unsigned int)(GRID - 1)) {
            // Last block: all accumulator atomics are L2-visible.
            double diff2d = atomicAdd(&g_acc[0], 0.0);
            double G2d    = atomicAdd(&g_acc[1], 0.0);
            double H2d    = atomicAdd(&g_acc[2], 0.0);
            out[0] = (float)(diff2d / G2d + LAMBDA * (diff2d / H2d));
            // Reset state for the next graph replay; no other thread-0 is
            // still touching these, and stream order protects later launches.
            atomicExch((unsigned long long*)&g_acc[0], 0ull);
            atomicExch((unsigned long long*)&g_acc[1], 0ull);
            atomicExch((unsigned long long*)&g_acc[2], 0ull);
            __threadfence();
            atomicExch(&g_count, 0u);
        }
    }
}

extern "C" void kernel_launch(void* const* d_in, const int* in_sizes, int n_in,
                              void* d_out, int out_size) {
    const float4* est = (const float4*)d_in[0];
    const float4* gt  = (const float4*)d_in[1];
    float* out = (float*)d_out;

    praloss_fused_kernel<<<GRID, TPB>>>(est, gt, out);
}